// round 11
// baseline (speedup 1.0000x reference)
#include <cuda_runtime.h>
#include <math.h>

// Problem constants: N_OBJ=1024, C_DET=8, C_SEG=4, H=W=28
#define C_DET 8
#define C_SEG 4
#define HW4 196          // 28*28/4 (float4 units)
#define N_OBJ 1024
#define NB 8             // objects per block (one per warp)
#define NCHUNK (N_OBJ / NB)   // 128
#define RTHREADS 256
#define NITER ((HW4 + 31) / 32)   // 7
#define MAX_EDGES 64

// Global double accumulators: [c][0]=denom, [c][1..4]=A[c][s].
// Zero at module load; finalize re-zeroes after reading -> every replay
// starts from zero. No zeroing kernel, no ticket.
__device__ double g_acc[C_DET][5];
__device__ float  g_sink;   // DCE-blocker for the L2 warm-up

// Streaming reduction: block=(chunk, det class), warp=object.
// Plain loads (no .cs — evict-first hurt LTS efficiency), no register cap
// (forcing <=36 regs was measured slower despite higher occupancy).
__global__ __launch_bounds__(RTHREADS) void reduce_kernel(
    const float4* __restrict__ det4,   // (N,C_DET,HW4) float4
    const float4* __restrict__ seg4,   // (N,C_DET,C_SEG,HW4) float4
    const float4* __restrict__ dcp4,   // (N_OBJ, C_DET) as float4
    const int*    __restrict__ edge_i,
    const int*    __restrict__ edge_j,
    int n_edges)
{
    const int c   = blockIdx.y;
    const int wid = threadIdx.x >> 5;
    const int lid = threadIdx.x & 31;
    const int n   = blockIdx.x * NB + wid;

    const size_t mb = (size_t)n * C_DET + c;
    const float4* __restrict__ dp = det4 + mb * HW4;
    const float4* __restrict__ sp = seg4 + mb * (C_SEG * HW4);

    float dsum = 0.0f;
    float a0 = 0.0f, a1 = 0.0f, a2 = 0.0f, a3 = 0.0f;

    #pragma unroll
    for (int it = 0; it < NITER; it++) {
        const int q = lid + it * 32;
        if (q < HW4) {
            const float4 d  = dp[q];
            const float4 s0 = sp[0 * HW4 + q];
            const float4 s1 = sp[1 * HW4 + q];
            const float4 s2 = sp[2 * HW4 + q];
            const float4 s3 = sp[3 * HW4 + q];
            dsum += (d.x + d.y) + (d.z + d.w);
            a0 += d.x * s0.x + d.y * s0.y + d.z * s0.z + d.w * s0.w;
            a1 += d.x * s1.x + d.y * s1.y + d.z * s1.z + d.w * s1.w;
            a2 += d.x * s2.x + d.y * s2.y + d.z * s2.z + d.w * s2.w;
            a3 += d.x * s3.x + d.y * s3.y + d.z * s3.z + d.w * s3.w;
        }
    }

    #pragma unroll
    for (int off = 16; off; off >>= 1) {
        dsum += __shfl_xor_sync(0xFFFFFFFFu, dsum, off);
        a0   += __shfl_xor_sync(0xFFFFFFFFu, a0, off);
        a1   += __shfl_xor_sync(0xFFFFFFFFu, a1, off);
        a2   += __shfl_xor_sync(0xFFFFFFFFu, a2, off);
        a3   += __shfl_xor_sync(0xFFFFFFFFu, a3, off);
    }

    __shared__ float sm[5][RTHREADS / 32];
    if (lid == 0) {
        sm[0][wid] = dsum; sm[1][wid] = a0; sm[2][wid] = a1;
        sm[3][wid] = a2;   sm[4][wid] = a3;
    }
    __syncthreads();

    if (threadIdx.x < 5) {              // 5 double atomics per block, 40 targets
        const int k = threadIdx.x;
        float r = 0.0f;
        #pragma unroll
        for (int w = 0; w < RTHREADS / 32; w++) r += sm[k][w];
        atomicAdd(&g_acc[c][k], (double)r);
    }

    // L2 warm-up for finalize (one block).
    if (blockIdx.x == 0 && c == 0) {
        float acc2 = 0.0f;
        for (int i = threadIdx.x; i < N_OBJ * C_DET / 4; i += RTHREADS) {
            const float4 v = __ldcg(dcp4 + i);
            acc2 += v.x + v.y + v.z + v.w;
        }
        if (threadIdx.x < n_edges)
            acc2 += (float)(__ldcg(edge_i + threadIdx.x) + __ldcg(edge_j + threadIdx.x));
        if (threadIdx.x == 0) g_sink = acc2;  // deterministic overwrite
    }
}

// Minimal finalize, PDL-overlapped: prologue (edges + dcp) runs under the
// reduce's tail; g_acc is consumed only after cudaGridDependencySynchronize.
__global__ __launch_bounds__(N_OBJ) void finalize_kernel(
    const float* __restrict__ dcp,       // (N_OBJ, C_DET)
    const int* __restrict__ edge_i,      // int32
    const int* __restrict__ edge_j,
    int n_edges,
    float* __restrict__ out)
{
    __shared__ double s_acc[C_DET][5];
    __shared__ float  s_w[C_DET];
    __shared__ float  red[N_OBJ / 32];
    __shared__ int    s_ei[MAX_EDGES], s_ej[MAX_EDGES];
    const int t = threadIdx.x;
    const int lid = t & 31;

    // --- PDL prologue: loads independent of the reduce ---
    if (t < n_edges) { s_ei[t] = edge_i[t]; s_ej[t] = edge_j[t]; }
    const float4* dcp4 = (const float4*)dcp;
    const float4 d0 = dcp4[t * 2 + 0];
    const float4 d1 = dcp4[t * 2 + 1];

    // Wait for the reduce grid's writes (g_acc) to be visible.
    cudaGridDependencySynchronize();

    if (t < C_DET * 5) ((double*)s_acc)[t] = ((const double*)g_acc)[t];
    __syncthreads();

    // Re-zero accumulators for the next replay (after everyone read them).
    if (t < C_DET * 5) ((double*)g_acc)[t] = 0.0;

    // Edge weights (deterministic fixed-order scan, atomic-free).
    if (t < C_DET) {
        double acc = 0.0;
        for (int e = 0; e < n_edges; e++)
            if (s_ej[e] == t)
                acc += s_acc[t][1 + s_ei[e]] / s_acc[t][0];
        s_w[t] = (float)acc;
    }
    __syncthreads();

    // Per-object prob + BCE mean (one object per thread).
    float w[C_DET];
    #pragma unroll
    for (int k = 0; k < C_DET; k++) w[k] = s_w[k];

    float p = d0.x * w[0] + d0.y * w[1] + d0.z * w[2] + d0.w * w[3]
            + d1.x * w[4] + d1.y * w[5] + d1.z * w[6] + d1.w * w[7];
    float l = -fmaxf(logf(p), -100.0f);

    #pragma unroll
    for (int off = 16; off; off >>= 1) l += __shfl_xor_sync(0xFFFFFFFFu, l, off);
    if (lid == 0) red[t >> 5] = l;
    __syncthreads();

    if (t < 32) {
        float v = red[t];
        #pragma unroll
        for (int off = 16; off; off >>= 1) v += __shfl_xor_sync(0xFFFFFFFFu, v, off);
        if (t == 0) out[0] = v / (float)N_OBJ;
    }
}

extern "C" void kernel_launch(void* const* d_in, const int* in_sizes, int n_in,
                              void* d_out, int out_size) {
    // metadata order: det_class_probs (f32), det_mask_probs (f32),
    //                 seg_mask_probs (f32), edge_i (i32), edge_j (i32)
    const float*  dcp = (const float*)d_in[0];
    const float4* det = (const float4*)d_in[1];
    const float4* seg = (const float4*)d_in[2];
    const int*    ei  = (const int*)d_in[3];
    const int*    ej  = (const int*)d_in[4];
    const int n_edges = in_sizes[3] < MAX_EDGES ? in_sizes[3] : MAX_EDGES;
    float* out = (float*)d_out;

    reduce_kernel<<<dim3(NCHUNK, C_DET), RTHREADS>>>(det, seg, (const float4*)dcp, ei, ej, n_edges);

    // Finalize with programmatic dependent launch: overlap its launch +
    // prologue with the reduce's tail.
    cudaLaunchConfig_t cfg = {};
    cfg.gridDim  = dim3(1, 1, 1);
    cfg.blockDim = dim3(N_OBJ, 1, 1);
    cfg.dynamicSmemBytes = 0;
    cfg.stream = 0;
    cudaLaunchAttribute attrs[1];
    attrs[0].id = cudaLaunchAttributeProgrammaticStreamSerialization;
    attrs[0].val.programmaticStreamSerializationAllowed = 1;
    cfg.attrs = attrs;
    cfg.numAttrs = 1;
    cudaLaunchKernelEx(&cfg, finalize_kernel, dcp, ei, ej, n_edges, out);
}

// round 12
// speedup vs baseline: 1.0626x; 1.0626x over previous
#include <cuda_runtime.h>
#include <math.h>

// Problem constants: N_OBJ=1024, C_DET=8, C_SEG=4, H=W=28
#define C_DET 8
#define C_SEG 4
#define HW4 196          // 28*28/4 (float4 units)
#define N_OBJ 1024
#define NB 8             // objects per block
#define NCHUNK (N_OBJ / NB)   // 128
#define RTHREADS 256
#define MAX_EDGES 64

// Global double accumulators: [c][0]=denom, [c][1..4]=A[c][s].
// Zero at module load; finalize re-zeroes after reading -> every replay
// starts from zero. No zeroing kernel.
__device__ double g_acc[C_DET][5];

// Streaming reduction — the R2 loop shape (best measured): thread t walks
// interleaved (object, quad) pairs so each block keeps 8 det + 32 seg
// streams concurrently in flight. Plain loads. Reg cap -> single wave.
__global__ __launch_bounds__(RTHREADS, 7) void reduce_kernel(
    const float4* __restrict__ det4,   // (N,C_DET,HW4) float4
    const float4* __restrict__ seg4)   // (N,C_DET,C_SEG,HW4) float4
{
    const int c  = blockIdx.y;
    const int n0 = blockIdx.x * NB;

    float dsum = 0.0f;
    float a0 = 0.0f, a1 = 0.0f, a2 = 0.0f, a3 = 0.0f;

    for (int t = threadIdx.x; t < NB * HW4; t += RTHREADS) {
        const int nl = t / HW4;
        const int q  = t - nl * HW4;
        const size_t m = (size_t)(n0 + nl) * C_DET + c;

        const float4 d = det4[m * HW4 + q];
        dsum += (d.x + d.y) + (d.z + d.w);

        const size_t sb = m * (C_SEG * HW4) + q;
        float4 v;
        v = seg4[sb + 0 * HW4]; a0 += d.x * v.x + d.y * v.y + d.z * v.z + d.w * v.w;
        v = seg4[sb + 1 * HW4]; a1 += d.x * v.x + d.y * v.y + d.z * v.z + d.w * v.w;
        v = seg4[sb + 2 * HW4]; a2 += d.x * v.x + d.y * v.y + d.z * v.z + d.w * v.w;
        v = seg4[sb + 3 * HW4]; a3 += d.x * v.x + d.y * v.y + d.z * v.z + d.w * v.w;
    }

    // Warp reduce 5 scalars
    #pragma unroll
    for (int off = 16; off; off >>= 1) {
        dsum += __shfl_xor_sync(0xFFFFFFFFu, dsum, off);
        a0   += __shfl_xor_sync(0xFFFFFFFFu, a0, off);
        a1   += __shfl_xor_sync(0xFFFFFFFFu, a1, off);
        a2   += __shfl_xor_sync(0xFFFFFFFFu, a2, off);
        a3   += __shfl_xor_sync(0xFFFFFFFFu, a3, off);
    }

    __shared__ float sm[5][RTHREADS / 32];
    const int wid = threadIdx.x >> 5;
    const int lid = threadIdx.x & 31;
    if (lid == 0) {
        sm[0][wid] = dsum; sm[1][wid] = a0; sm[2][wid] = a1;
        sm[3][wid] = a2;   sm[4][wid] = a3;
    }
    __syncthreads();

    if (threadIdx.x < 5) {              // 5 double atomics per block, 40 targets
        const int k = threadIdx.x;
        float r = 0.0f;
        #pragma unroll
        for (int w = 0; w < RTHREADS / 32; w++) r += sm[k][w];
        atomicAdd(&g_acc[c][k], (double)r);
    }
}

// Minimal finalize: parallel loads (edges, accumulators, dcp) in one latency
// round; deterministic fixed-order edge-weight build; self-zeroes g_acc.
__global__ __launch_bounds__(N_OBJ) void finalize_kernel(
    const float* __restrict__ dcp,       // (N_OBJ, C_DET)
    const int* __restrict__ edge_i,      // int32
    const int* __restrict__ edge_j,
    int n_edges,
    float* __restrict__ out)
{
    __shared__ double s_acc[C_DET][5];
    __shared__ float  s_w[C_DET];
    __shared__ float  red[N_OBJ / 32];
    __shared__ int    s_ei[MAX_EDGES], s_ej[MAX_EDGES];
    const int t = threadIdx.x;
    const int lid = t & 31;

    if (t < n_edges) { s_ei[t] = edge_i[t]; s_ej[t] = edge_j[t]; }
    if (t < C_DET * 5) ((double*)s_acc)[t] = ((const double*)g_acc)[t];

    const float4* dcp4 = (const float4*)dcp;
    const float4 d0 = dcp4[t * 2 + 0];
    const float4 d1 = dcp4[t * 2 + 1];
    __syncthreads();

    // Re-zero accumulators for the next replay (after everyone read them).
    if (t < C_DET * 5) ((double*)g_acc)[t] = 0.0;

    // Edge weights (deterministic fixed-order scan, atomic-free).
    if (t < C_DET) {
        double acc = 0.0;
        for (int e = 0; e < n_edges; e++)
            if (s_ej[e] == t)
                acc += s_acc[t][1 + s_ei[e]] / s_acc[t][0];
        s_w[t] = (float)acc;
    }
    __syncthreads();

    // Per-object prob + BCE mean (one object per thread).
    float w[C_DET];
    #pragma unroll
    for (int k = 0; k < C_DET; k++) w[k] = s_w[k];

    float p = d0.x * w[0] + d0.y * w[1] + d0.z * w[2] + d0.w * w[3]
            + d1.x * w[4] + d1.y * w[5] + d1.z * w[6] + d1.w * w[7];
    float l = -fmaxf(logf(p), -100.0f);

    #pragma unroll
    for (int off = 16; off; off >>= 1) l += __shfl_xor_sync(0xFFFFFFFFu, l, off);
    if (lid == 0) red[t >> 5] = l;
    __syncthreads();

    if (t < 32) {
        float v = red[t];
        #pragma unroll
        for (int off = 16; off; off >>= 1) v += __shfl_xor_sync(0xFFFFFFFFu, v, off);
        if (t == 0) out[0] = v / (float)N_OBJ;
    }
}

extern "C" void kernel_launch(void* const* d_in, const int* in_sizes, int n_in,
                              void* d_out, int out_size) {
    // metadata order: det_class_probs (f32), det_mask_probs (f32),
    //                 seg_mask_probs (f32), edge_i (i32), edge_j (i32)
    const float*  dcp = (const float*)d_in[0];
    const float4* det = (const float4*)d_in[1];
    const float4* seg = (const float4*)d_in[2];
    const int*    ei  = (const int*)d_in[3];
    const int*    ej  = (const int*)d_in[4];
    const int n_edges = in_sizes[3] < MAX_EDGES ? in_sizes[3] : MAX_EDGES;
    float* out = (float*)d_out;

    reduce_kernel<<<dim3(NCHUNK, C_DET), RTHREADS>>>(det, seg);
    finalize_kernel<<<1, N_OBJ>>>(dcp, ei, ej, n_edges, out);
}